// round 3
// baseline (speedup 1.0000x reference)
#include <cuda_runtime.h>
#include <cuda_bf16.h>
#include <cstdint>

// Problem shape constants (fixed by setup_inputs)
#define MAX_NODES 100000
#define MAX_EDGES 1600000
#define D_IN   256
#define D_HALF 128
#define D_OUT  256   // concat(forward, backward)

// ---------------- device scratch (no allocations allowed) ----------------
__device__ int   g_is64;                     // 1 if edge_index is int64, else int32
__device__ int   g_deg_in [MAX_NODES];       // edge-only in-degree (col)
__device__ int   g_deg_out[MAX_NODES];       // edge-only out-degree (row)
__device__ int   g_off_in [MAX_NODES + 1];
__device__ int   g_off_out[MAX_NODES + 1];
__device__ int   g_fill_in [MAX_NODES];
__device__ int   g_fill_out[MAX_NODES];
__device__ int   g_src_f[MAX_EDGES];         // for target c: list of sources r
__device__ int   g_src_b[MAX_EDGES];         // for target r: list of sources c
__device__ float g_rin [MAX_NODES];
__device__ float g_rout[MAX_NODES];
__device__ float g_feat[(size_t)MAX_NODES * D_OUT]; // [node][0:128]=x@Wf^T, [128:256]=x@Wb^T

// Edge accessors: w = edge buffer viewed as 32-bit words.
// int64 layout: col[e] at word 2e (hi word 0), row[e] at word 2*(n_edges+e).
// int32 layout: col[e] at word e,              row[e] at word n_edges+e.
__device__ __forceinline__ int edge_col(const unsigned* __restrict__ w, int e, int is64) {
    return (int)(is64 ? w[2u * (unsigned)e] : w[(unsigned)e]);
}
__device__ __forceinline__ int edge_row(const unsigned* __restrict__ w, int e, int n_edges, int is64) {
    return (int)(is64 ? w[2u * (unsigned)(n_edges + e)] : w[(unsigned)(n_edges + e)]);
}

// ---------------- K_detect: decide edge dtype from data ----------------
__global__ void k_detect(const unsigned* __restrict__ w, int n_words_check) {
    __shared__ unsigned s[256];
    unsigned acc = 0;
    for (int i = threadIdx.x; i < n_words_check; i += 256)
        if (i & 1) acc |= w[i];
    s[threadIdx.x] = acc;
    __syncthreads();
    for (int d = 128; d > 0; d >>= 1) {
        if (threadIdx.x < d) s[threadIdx.x] |= s[threadIdx.x + d];
        __syncthreads();
    }
    if (threadIdx.x == 0) g_is64 = (s[0] == 0) ? 1 : 0;
}

// ---------------- K0: zero counters ----------------
__global__ void k_zero(int n_nodes) {
    int i = blockIdx.x * blockDim.x + threadIdx.x;
    if (i < n_nodes) {
        g_deg_in[i]   = 0;
        g_deg_out[i]  = 0;
        g_fill_in[i]  = 0;
        g_fill_out[i] = 0;
    }
}

// ---------------- K1: degree histograms ----------------
__global__ void k_hist(const unsigned* __restrict__ w, int n_edges) {
    int e = blockIdx.x * blockDim.x + threadIdx.x;
    if (e < n_edges) {
        int is64 = g_is64;
        atomicAdd(&g_deg_in [edge_col(w, e, is64)], 1);
        atomicAdd(&g_deg_out[edge_row(w, e, n_edges, is64)], 1);
    }
}

// ---------------- K2: single-block packed exclusive scan + rsqrt ----------------
// Packs (deg_out << 32 | deg_in) into one 64-bit value; both sums < 2^31 so no
// carry between fields. Also writes rin/rout = rsqrt(deg + 1)  (self loop).
__global__ __launch_bounds__(1024)
void k_scan(int n_nodes) {
    const int T = 1024, V = 4, CH = T * V;
    __shared__ long long warpsum[32];
    const int tid  = threadIdx.x;
    const int lane = tid & 31;
    const int wid  = tid >> 5;
    long long run = 0;

    for (int base = 0; base < n_nodes; base += CH) {
        long long v[V];
        long long s = 0;
        int i0 = base + tid * V;
#pragma unroll
        for (int j = 0; j < V; j++) {
            int i = i0 + j;
            long long din = 0, dout = 0;
            if (i < n_nodes) {
                din  = g_deg_in[i];
                dout = g_deg_out[i];
                g_rin [i] = rsqrtf((float)(din  + 1));
                g_rout[i] = rsqrtf((float)(dout + 1));
            }
            v[j] = (dout << 32) | din;
            s += v[j];
        }
        long long t = s;
#pragma unroll
        for (int d = 1; d < 32; d <<= 1) {
            long long u = __shfl_up_sync(0xffffffff, t, d);
            if (lane >= d) t += u;
        }
        if (lane == 31) warpsum[wid] = t;
        __syncthreads();
        if (wid == 0) {
            long long wv = warpsum[lane];
#pragma unroll
            for (int d = 1; d < 32; d <<= 1) {
                long long u = __shfl_up_sync(0xffffffff, wv, d);
                if (lane >= d) wv += u;
            }
            warpsum[lane] = wv;
        }
        __syncthreads();
        long long warpoff = (wid > 0) ? warpsum[wid - 1] : 0;
        long long excl = run + warpoff + (t - s);
#pragma unroll
        for (int j = 0; j < V; j++) {
            int i = i0 + j;
            if (i < n_nodes) {
                g_off_in [i] = (int)(excl & 0xffffffffLL);
                g_off_out[i] = (int)((unsigned long long)excl >> 32);
            }
            excl += v[j];
        }
        run += warpsum[31];
        __syncthreads();
    }
    if (tid == 0) {
        g_off_in [n_nodes] = (int)(run & 0xffffffffLL);
        g_off_out[n_nodes] = (int)((unsigned long long)run >> 32);
    }
}

// ---------------- K3: bucket fill ----------------
__global__ void k_fill(const unsigned* __restrict__ w, int n_edges) {
    int e = blockIdx.x * blockDim.x + threadIdx.x;
    if (e >= n_edges) return;
    int is64 = g_is64;
    int c = edge_col(w, e, is64);
    int r = edge_row(w, e, n_edges, is64);
    int p = atomicAdd(&g_fill_in[c], 1);
    g_src_f[g_off_in[c] + p] = r;
    int q = atomicAdd(&g_fill_out[r], 1);
    g_src_b[g_off_out[r] + q] = c;
}

// ---------------- K4: GEMM  feat = x @ [Wf;Wb]^T ----------------
#define BM 64
#define BN 128
#define BK 32
__global__ __launch_bounds__(256)
void k_gemm(const float* __restrict__ x,
            const float* __restrict__ Wf,
            const float* __restrict__ Wb,
            int n_nodes) {
    __shared__ float sx[BK][BM];
    __shared__ float sw[BK][BN];

    const int half = blockIdx.y;               // 0 -> Wf (cols 0..127), 1 -> Wb (cols 128..255)
    const float* __restrict__ W = half ? Wb : Wf;
    const int row0 = blockIdx.x * BM;
    const int t  = threadIdx.x;
    const int tx = t & 15;                     // 16 col-threads
    const int ty = t >> 4;                     // 16 row-threads

    float acc[4][8];
#pragma unroll
    for (int i = 0; i < 4; i++)
#pragma unroll
        for (int j = 0; j < 8; j++) acc[i][j] = 0.f;

    for (int k0 = 0; k0 < D_IN; k0 += BK) {
#pragma unroll
        for (int i = 0; i < 2; i++) {
            int idx = t * 2 + i;               // 0..511
            int m   = idx >> 3;                // 0..63
            int kk  = (idx & 7) * 4;           // 0,4,...,28
            float4 v = make_float4(0.f, 0.f, 0.f, 0.f);
            if (row0 + m < n_nodes)
                v = *(const float4*)(x + (size_t)(row0 + m) * D_IN + k0 + kk);
            sx[kk + 0][m] = v.x; sx[kk + 1][m] = v.y;
            sx[kk + 2][m] = v.z; sx[kk + 3][m] = v.w;
        }
#pragma unroll
        for (int i = 0; i < 4; i++) {
            int idx = t * 4 + i;               // 0..1023
            int n   = idx >> 3;                // 0..127
            int kk  = (idx & 7) * 4;
            float4 v = *(const float4*)(W + (size_t)n * D_IN + k0 + kk);
            sw[kk + 0][n] = v.x; sw[kk + 1][n] = v.y;
            sw[kk + 2][n] = v.z; sw[kk + 3][n] = v.w;
        }
        __syncthreads();

#pragma unroll
        for (int kk = 0; kk < BK; kk++) {
            float a[4], b[8];
#pragma unroll
            for (int i = 0; i < 4; i++) a[i] = sx[kk][ty * 4 + i];
#pragma unroll
            for (int j = 0; j < 8; j++) b[j] = sw[kk][tx + 16 * j];
#pragma unroll
            for (int i = 0; i < 4; i++)
#pragma unroll
                for (int j = 0; j < 8; j++)
                    acc[i][j] = fmaf(a[i], b[j], acc[i][j]);
        }
        __syncthreads();
    }

#pragma unroll
    for (int i = 0; i < 4; i++) {
        int node = row0 + ty * 4 + i;
        if (node < n_nodes) {
            float* out = g_feat + (size_t)node * D_OUT + half * D_HALF;
#pragma unroll
            for (int j = 0; j < 8; j++)
                out[tx + 16 * j] = acc[i][j];
        }
    }
}

// ---------------- K5: gather (one block per node, fwd + bwd halves) ----------------
__global__ __launch_bounds__(256)
void k_gather(const float* __restrict__ bias, float* __restrict__ y, int n_nodes) {
    const int node = blockIdx.x;
    const int tid  = threadIdx.x;

    if (tid < D_HALF) {
        // forward: y_f[node] = bias + rin[node]*(rout[node]*xf[node] + sum rout[r]*xf[r])
        const int j = tid;
        float acc = g_rout[node] * g_feat[(size_t)node * D_OUT + j];   // self loop
        const int s = g_off_in[node], e = g_off_in[node + 1];
        for (int k = s; k < e; k++) {
            int r = __ldg(&g_src_f[k]);
            acc += g_rout[r] * __ldg(&g_feat[(size_t)r * D_OUT + j]);
        }
        y[(size_t)node * D_OUT + j] = bias[j] + g_rin[node] * acc;
    } else {
        // backward: y_b[node] = bias + rout[node]*(rin[node]*xb[node] + sum rin[c]*xb[c])
        const int j = tid;                       // 128..255 -> feat col 128..255
        float acc = g_rin[node] * g_feat[(size_t)node * D_OUT + j];    // self loop
        const int s = g_off_out[node], e = g_off_out[node + 1];
        for (int k = s; k < e; k++) {
            int c = __ldg(&g_src_b[k]);
            acc += g_rin[c] * __ldg(&g_feat[(size_t)c * D_OUT + j]);
        }
        y[(size_t)node * D_OUT + j] = bias[j] + g_rout[node] * acc;
    }
}

// ---------------- launch ----------------
extern "C" void kernel_launch(void* const* d_in, const int* in_sizes, int n_in,
                              void* d_out, int out_size) {
    const float*    x    = (const float*)d_in[0];
    const unsigned* ew   = (const unsigned*)d_in[1];   // edge words (dtype detected on device)
    const float*    Wf   = (const float*)d_in[2];
    const float*    Wb   = (const float*)d_in[3];
    const float*    bias = (const float*)d_in[4];
    float* y = (float*)d_out;

    const int n_nodes = in_sizes[0] / D_IN;
    const int n_edges = in_sizes[1] / 2;   // element count -> edges (same for i32/i64)

    // dtype detection: check 8192 words (buffer has >= 2*n_edges >= that)
    int check = 8192;
    if (check > 2 * n_edges) check = 2 * n_edges;
    k_detect<<<1, 256>>>(ew, check);

    k_zero<<<(n_nodes + 255) / 256, 256>>>(n_nodes);
    k_hist<<<(n_edges + 255) / 256, 256>>>(ew, n_edges);
    k_scan<<<1, 1024>>>(n_nodes);
    k_fill<<<(n_edges + 255) / 256, 256>>>(ew, n_edges);

    dim3 ggrid((n_nodes + BM - 1) / BM, 2);
    k_gemm<<<ggrid, 256>>>(x, Wf, Wb, n_nodes);

    k_gather<<<n_nodes, 256>>>(bias, y, n_nodes);
}

// round 5
// speedup vs baseline: 1.2309x; 1.2309x over previous
#include <cuda_runtime.h>
#include <cuda_bf16.h>
#include <cstdint>

// Problem shape constants (fixed by setup_inputs)
#define MAX_NODES 100000
#define MAX_EDGES 1600000
#define D_IN   256
#define D_HALF 128
#define D_OUT  256   // concat(forward, backward)

#define SCAN_CH 2048        // elems per scan block (512 thr * 4)
#define MAX_SCAN_BLOCKS 64

// ---------------- device scratch (no allocations allowed) ----------------
__device__ int   g_is64;
__device__ int   g_deg_in [MAX_NODES];
__device__ int   g_deg_out[MAX_NODES];
__device__ int   g_off_in [MAX_NODES + 1];
__device__ int   g_off_out[MAX_NODES + 1];
__device__ int   g_fill_in [MAX_NODES];
__device__ int   g_fill_out[MAX_NODES];
__device__ int   g_src_f[MAX_EDGES];
__device__ int   g_src_b[MAX_EDGES];
__device__ float g_rin [MAX_NODES];
__device__ float g_rout[MAX_NODES];
__device__ long long g_bsum[MAX_SCAN_BLOCKS];
__device__ float g_feat[(size_t)MAX_NODES * D_OUT];       // fp32 features for gather
__device__ __nv_bfloat16 g_xhi[(size_t)MAX_NODES * D_IN]; // bf16 split of x
__device__ __nv_bfloat16 g_xlo[(size_t)MAX_NODES * D_IN];
__device__ __nv_bfloat16 g_wb [(size_t)256 * 768];        // B [n][768]: cols 0-255 Whi, 256-511 Whi, 512-767 Wlo

// ---------------- edge accessors (dtype detected at runtime) ----------------
__device__ __forceinline__ int edge_col(const unsigned* __restrict__ w, int e, int is64) {
    return (int)(is64 ? w[2u * (unsigned)e] : w[(unsigned)e]);
}
__device__ __forceinline__ int edge_row(const unsigned* __restrict__ w, int e, int n_edges, int is64) {
    return (int)(is64 ? w[2u * (unsigned)(n_edges + e)] : w[(unsigned)(n_edges + e)]);
}

__global__ void k_detect(const unsigned* __restrict__ w, int n_words_check) {
    __shared__ unsigned s[256];
    unsigned acc = 0;
    for (int i = threadIdx.x; i < n_words_check; i += 256)
        if (i & 1) acc |= w[i];
    s[threadIdx.x] = acc;
    __syncthreads();
    for (int d = 128; d > 0; d >>= 1) {
        if (threadIdx.x < d) s[threadIdx.x] |= s[threadIdx.x + d];
        __syncthreads();
    }
    if (threadIdx.x == 0) g_is64 = (s[0] == 0) ? 1 : 0;
}

__global__ void k_zero(int n_nodes) {
    int i = blockIdx.x * blockDim.x + threadIdx.x;
    if (i < n_nodes) {
        g_deg_in[i]   = 0;
        g_deg_out[i]  = 0;
        g_fill_in[i]  = 0;
        g_fill_out[i] = 0;
    }
}

__global__ void k_hist(const unsigned* __restrict__ w, int n_edges) {
    int e = blockIdx.x * blockDim.x + threadIdx.x;
    if (e < n_edges) {
        int is64 = g_is64;
        atomicAdd(&g_deg_in [edge_col(w, e, is64)], 1);
        atomicAdd(&g_deg_out[edge_row(w, e, n_edges, is64)], 1);
    }
}

// ---------------- multi-block packed exclusive scan ----------------
__global__ __launch_bounds__(512)
void k_scan_part(int n_nodes) {
    __shared__ long long ws[16];
    const int tid = threadIdx.x, lane = tid & 31, wid = tid >> 5;
    int i0 = blockIdx.x * SCAN_CH + tid * 4;
    long long s = 0;
#pragma unroll
    for (int j = 0; j < 4; j++) {
        int i = i0 + j;
        if (i < n_nodes)
            s += ((long long)g_deg_out[i] << 32) | (unsigned)g_deg_in[i];
    }
#pragma unroll
    for (int d = 16; d > 0; d >>= 1) s += __shfl_down_sync(0xffffffff, s, d);
    if (lane == 0) ws[wid] = s;
    __syncthreads();
    if (wid == 0) {
        long long r = (lane < 16) ? ws[lane] : 0;
#pragma unroll
        for (int d = 8; d > 0; d >>= 1) r += __shfl_down_sync(0xffffffff, r, d);
        if (lane == 0) g_bsum[blockIdx.x] = r;
    }
}

__global__ void k_scan_bsum(int nb) {
    int tid = threadIdx.x;                 // 64 threads
    long long v = (tid < nb) ? g_bsum[tid] : 0;
    long long t = v;
#pragma unroll
    for (int d = 1; d < 32; d <<= 1) {
        long long u = __shfl_up_sync(0xffffffff, t, d);
        if ((tid & 31) >= d) t += u;
    }
    __shared__ long long w0tot;
    if (tid == 31) w0tot = t;
    __syncthreads();
    if (tid >= 32) t += w0tot;
    if (tid < nb) g_bsum[tid] = t - v;     // exclusive
}

__global__ __launch_bounds__(512)
void k_scan_final(int n_nodes) {
    __shared__ long long warpsum[16];
    const int tid = threadIdx.x, lane = tid & 31, wid = tid >> 5;
    const long long run = g_bsum[blockIdx.x];
    int i0 = blockIdx.x * SCAN_CH + tid * 4;
    long long v[4];
    long long s = 0;
#pragma unroll
    for (int j = 0; j < 4; j++) {
        int i = i0 + j;
        long long din = 0, dout = 0;
        if (i < n_nodes) {
            din  = g_deg_in[i];
            dout = g_deg_out[i];
            g_rin [i] = rsqrtf((float)(din  + 1));   // +1 self loop
            g_rout[i] = rsqrtf((float)(dout + 1));
        }
        v[j] = (dout << 32) | din;
        s += v[j];
    }
    long long t = s;
#pragma unroll
    for (int d = 1; d < 32; d <<= 1) {
        long long u = __shfl_up_sync(0xffffffff, t, d);
        if (lane >= d) t += u;
    }
    if (lane == 31) warpsum[wid] = t;
    __syncthreads();
    if (wid == 0) {
        long long w = (lane < 16) ? warpsum[lane] : 0;
#pragma unroll
        for (int d = 1; d < 16; d <<= 1) {
            long long u = __shfl_up_sync(0xffffffff, w, d);
            if (lane >= d) w += u;
        }
        if (lane < 16) warpsum[lane] = w;
    }
    __syncthreads();
    long long warpoff = (wid > 0) ? warpsum[wid - 1] : 0;
    long long excl = run + warpoff + (t - s);
#pragma unroll
    for (int j = 0; j < 4; j++) {
        int i = i0 + j;
        if (i < n_nodes) {
            g_off_in [i] = (int)(excl & 0xffffffffLL);
            g_off_out[i] = (int)((unsigned long long)excl >> 32);
        }
        excl += v[j];
        if (i == n_nodes - 1) {
            g_off_in [n_nodes] = (int)(excl & 0xffffffffLL);
            g_off_out[n_nodes] = (int)((unsigned long long)excl >> 32);
        }
    }
}

__global__ void k_fill(const unsigned* __restrict__ w, int n_edges) {
    int e = blockIdx.x * blockDim.x + threadIdx.x;
    if (e >= n_edges) return;
    int is64 = g_is64;
    int c = edge_col(w, e, is64);
    int r = edge_row(w, e, n_edges, is64);
    int p = atomicAdd(&g_fill_in[c], 1);
    g_src_f[g_off_in[c] + p] = r;
    int q = atomicAdd(&g_fill_out[r], 1);
    g_src_b[g_off_out[r] + q] = c;
}

// ---------------- bf16-split conversion kernels ----------------
__global__ void k_cvt_x(const float* __restrict__ x, int total4) {
    int idx = blockIdx.x * blockDim.x + threadIdx.x;
    if (idx >= total4) return;
    float4 v = ((const float4*)x)[idx];
    float vv[4] = {v.x, v.y, v.z, v.w};
    __nv_bfloat16 h[4], l[4];
#pragma unroll
    for (int j = 0; j < 4; j++) {
        h[j] = __float2bfloat16(vv[j]);
        l[j] = __float2bfloat16(vv[j] - __bfloat162float(h[j]));
    }
    *(uint2*)(g_xhi + (size_t)idx * 4) = *(uint2*)h;
    *(uint2*)(g_xlo + (size_t)idx * 4) = *(uint2*)l;
}

__global__ void k_prep_w(const float* __restrict__ Wf, const float* __restrict__ Wb) {
    int idx = blockIdx.x * blockDim.x + threadIdx.x;
    if (idx >= 256 * 768) return;
    int n = idx / 768;
    int k = idx % 768;
    int kk = k & 255;
    int sec = k >> 8;
    const float* Wsrc = (n < 128) ? (Wf + (size_t)n * D_IN) : (Wb + (size_t)(n - 128) * D_IN);
    float v = Wsrc[kk];
    __nv_bfloat16 hi = __float2bfloat16(v);
    g_wb[idx] = (sec < 2) ? hi : __float2bfloat16(v - __bfloat162float(hi));
}

// ---------------- mma.sync bf16 GEMM: feat = x @ [Wf;Wb]^T ----------------
// Block: 128 (M) x 64 (N), 256 threads = 8 warps as 4(M) x 2(N), warp tile 32x32.
// K = 768 (3 bf16-split sections of 256), BK = 32 per iteration.
#define SA_LD 48   // bf16 row stride (32 + 16 pad), 96B: uint4-aligned
__device__ __forceinline__ void mma16816(float* c, const uint32_t* a, const uint32_t* b) {
    asm volatile(
        "mma.sync.aligned.m16n8k16.row.col.f32.bf16.bf16.f32 "
        "{%0,%1,%2,%3}, {%4,%5,%6,%7}, {%8,%9}, {%0,%1,%2,%3};"
        : "+f"(c[0]), "+f"(c[1]), "+f"(c[2]), "+f"(c[3])
        : "r"(a[0]), "r"(a[1]), "r"(a[2]), "r"(a[3]), "r"(b[0]), "r"(b[1]));
}

__global__ __launch_bounds__(256, 2)
void k_gemm_mma(int n_nodes) {
    __shared__ __nv_bfloat16 sA[128 * SA_LD];
    __shared__ __nv_bfloat16 sB[64 * SA_LD];

    const int tid  = threadIdx.x;
    const int wid  = tid >> 5;
    const int lane = tid & 31;
    const int qr   = lane >> 2;          // 0..7
    const int qc   = lane & 3;           // 0..3
    const int wm   = (wid & 3) * 32;     // warp M offset in block
    const int wn   = (wid >> 2) * 32;    // warp N offset in block
    const int m0   = blockIdx.x * 128;
    const int n0   = blockIdx.y * 64;

    float acc[2][4][4];
#pragma unroll
    for (int mt = 0; mt < 2; mt++)
#pragma unroll
        for (int nt = 0; nt < 4; nt++)
#pragma unroll
            for (int q = 0; q < 4; q++) acc[mt][nt][q] = 0.f;

    for (int it = 0; it < 24; it++) {
        const int sec  = it >> 3;                  // 0:hi 1:lo 2:hi
        const int koff = (it & 7) * 32;
        const __nv_bfloat16* asrc = (sec == 1) ? g_xlo : g_xhi;

        // A tile 128x32 -> sA (512 uint4)
#pragma unroll
        for (int i = 0; i < 2; i++) {
            int seg  = tid + 256 * i;
            int row  = seg >> 2;
            int part = seg & 3;
            int node = m0 + row;
            if (node >= n_nodes) node = n_nodes - 1;
            uint4 v = *(const uint4*)(asrc + (size_t)node * D_IN + koff + part * 8);
            *(uint4*)(sA + row * SA_LD + part * 8) = v;
        }
        // B tile 64x32 -> sB (256 uint4)
        {
            int row  = tid >> 2;
            int part = tid & 3;
            uint4 v = *(const uint4*)(g_wb + (size_t)(n0 + row) * 768 + it * 32 + part * 8);
            *(uint4*)(sB + row * SA_LD + part * 8) = v;
        }
        __syncthreads();

#pragma unroll
        for (int ks = 0; ks < 2; ks++) {
            const int kb = ks * 16;
            uint32_t a[2][4], b[4][2];
#pragma unroll
            for (int mt = 0; mt < 2; mt++) {
                const __nv_bfloat16* base = sA + (wm + mt * 16 + qr) * SA_LD + kb + 2 * qc;
                a[mt][0] = *(const uint32_t*)(base);
                a[mt][1] = *(const uint32_t*)(base + 8 * SA_LD);
                a[mt][2] = *(const uint32_t*)(base + 8);
                a[mt][3] = *(const uint32_t*)(base + 8 * SA_LD + 8);
            }
#pragma unroll
            for (int nt = 0; nt < 4; nt++) {
                const __nv_bfloat16* base = sB + (wn + nt * 8 + qr) * SA_LD + kb + 2 * qc;
                b[nt][0] = *(const uint32_t*)(base);
                b[nt][1] = *(const uint32_t*)(base + 8);
            }
#pragma unroll
            for (int mt = 0; mt < 2; mt++)
#pragma unroll
                for (int nt = 0; nt < 4; nt++)
                    mma16816(acc[mt][nt], a[mt], b[nt]);
        }
        __syncthreads();
    }

    // epilogue: write g_feat
#pragma unroll
    for (int mt = 0; mt < 2; mt++) {
        int r0 = m0 + wm + mt * 16 + qr;
#pragma unroll
        for (int nt = 0; nt < 4; nt++) {
            int cix = n0 + wn + nt * 8 + 2 * qc;
            if (r0 < n_nodes) {
                float2 v = make_float2(acc[mt][nt][0], acc[mt][nt][1]);
                *(float2*)(g_feat + (size_t)r0 * D_OUT + cix) = v;
            }
            if (r0 + 8 < n_nodes) {
                float2 v = make_float2(acc[mt][nt][2], acc[mt][nt][3]);
                *(float2*)(g_feat + (size_t)(r0 + 8) * D_OUT + cix) = v;
            }
        }
    }
}

// ---------------- gather (one block per node, fwd + bwd halves) ----------------
__global__ __launch_bounds__(256)
void k_gather(const float* __restrict__ bias, float* __restrict__ y, int n_nodes) {
    const int node = blockIdx.x;
    const int tid  = threadIdx.x;

    if (tid < D_HALF) {
        const int j = tid;
        float acc = g_rout[node] * g_feat[(size_t)node * D_OUT + j];   // self loop
        const int s = g_off_in[node], e = g_off_in[node + 1];
        for (int k = s; k < e; k++) {
            int r = __ldg(&g_src_f[k]);
            acc += g_rout[r] * __ldg(&g_feat[(size_t)r * D_OUT + j]);
        }
        y[(size_t)node * D_OUT + j] = bias[j] + g_rin[node] * acc;
    } else {
        const int j = tid;
        float acc = g_rin[node] * g_feat[(size_t)node * D_OUT + j];    // self loop
        const int s = g_off_out[node], e = g_off_out[node + 1];
        for (int k = s; k < e; k++) {
            int c = __ldg(&g_src_b[k]);
            acc += g_rin[c] * __ldg(&g_feat[(size_t)c * D_OUT + j]);
        }
        y[(size_t)node * D_OUT + j] = bias[j] + g_rout[node] * acc;
    }
}

// ---------------- launch ----------------
extern "C" void kernel_launch(void* const* d_in, const int* in_sizes, int n_in,
                              void* d_out, int out_size) {
    const float*    x    = (const float*)d_in[0];
    const unsigned* ew   = (const unsigned*)d_in[1];
    const float*    Wf   = (const float*)d_in[2];
    const float*    Wb   = (const float*)d_in[3];
    const float*    bias = (const float*)d_in[4];
    float* y = (float*)d_out;

    const int n_nodes = in_sizes[0] / D_IN;
    const int n_edges = in_sizes[1] / 2;

    int check = 8192;
    if (check > 2 * n_edges) check = 2 * n_edges;
    k_detect<<<1, 256>>>(ew, check);

    k_zero<<<(n_nodes + 255) / 256, 256>>>(n_nodes);
    k_hist<<<(n_edges + 255) / 256, 256>>>(ew, n_edges);

    const int nb = (n_nodes + SCAN_CH - 1) / SCAN_CH;
    k_scan_part <<<nb, 512>>>(n_nodes);
    k_scan_bsum <<<1, 64>>>(nb);
    k_scan_final<<<nb, 512>>>(n_nodes);

    k_fill<<<(n_edges + 255) / 256, 256>>>(ew, n_edges);

    int total4 = n_nodes * (D_IN / 4);
    k_cvt_x <<<(total4 + 255) / 256, 256>>>(x, total4);
    k_prep_w<<<(256 * 768 + 255) / 256, 256>>>(Wf, Wb);

    dim3 ggrid((n_nodes + 127) / 128, 4);
    k_gemm_mma<<<ggrid, 256>>>(n_nodes);

    k_gather<<<n_nodes, 256>>>(bias, y, n_nodes);
}